// round 4
// baseline (speedup 1.0000x reference)
#include <cuda_runtime.h>

#define B_DIM 16
#define C_DIM 256
#define N_DIM 16384
#define K_DIM 8
#define NB 32
#define NTILES (N_DIM / NB)          // 512 tiles per b
#define GR 18                        // blocks per b (grid stride)
#define NSTAGES 10
#define KAPPA 20.0f

// ---- smem layout (floats) ----
// x tile: addr(c,n) = c*33 + 2*(c>>4) + n   (conflict-free for both phases)
#define SX_SIZE 8480                 // 255*33 + 30 + 32, padded
#define MU_OFF  (2 * SX_SIZE)        // 16960
#define MU_SIZE 2112                 // addr(c,k) = c*8 + 4*(c>>4)
#define Z_OFF   (MU_OFF + MU_SIZE)   // 19072 ; z[n][k], 32*8
#define M_OFF   (Z_OFF + 256)        // 19328 ; s_M[h][c][k] = 2*256*8
#define S_OFF   (M_OFF + 4096)       // 23424 ; s_S[8]
#define SM_FLOATS (S_OFF + 8)
#define SMEM_BYTES (SM_FLOATS * 4)

__device__ float g_mu[B_DIM * C_DIM * K_DIM];  // [b][c][k]
__device__ float g_M [B_DIM * C_DIM * K_DIM];  // accumulator [b][c][k]
__device__ float g_S [B_DIM * K_DIM];          // z column sums [b][k]

__device__ __forceinline__ float2 ffma2(float2 a, float2 b, float2 c) {
    float2 d;
    asm("fma.rn.f32x2 %0, %1, %2, %3;"
        : "=l"(reinterpret_cast<unsigned long long&>(d))
        : "l"(reinterpret_cast<unsigned long long&>(a)),
          "l"(reinterpret_cast<unsigned long long&>(b)),
          "l"(reinterpret_cast<unsigned long long&>(c)));
    return d;
}

__device__ __forceinline__ int SX(int c, int n) { return c * 33 + ((c >> 4) << 1) + n; }
__device__ __forceinline__ int MU(int c)        { return c * 8  + ((c >> 4) << 2); }

__global__ void init_kernel(const float* __restrict__ mu_in) {
    int idx = blockIdx.x * blockDim.x + threadIdx.x;
    if (idx < B_DIM * C_DIM * K_DIM) {
        g_mu[idx] = mu_in[idx & (C_DIM * K_DIM - 1)];
        g_M[idx]  = 0.0f;
    }
    if (idx < B_DIM * K_DIM) g_S[idx] = 0.0f;
}

__global__ __launch_bounds__(512, 2)
void em_stage(const float* __restrict__ x, int last, float* __restrict__ z_out) {
    extern __shared__ float sm[];
    float* s_mu = sm + MU_OFF;
    float* s_z  = sm + Z_OFF;
    float* s_M  = sm + M_OFF;
    float* s_S  = sm + S_OFF;

    const int tid = threadIdx.x;
    const int b   = blockIdx.y;
    const float* xb = x + (size_t)b * C_DIM * N_DIM;

    // loader mapping: c = tid>>1, h = tid&1 ; 16 floats each
    const int lc = tid >> 1;
    const int lh = tid & 1;
    const size_t gbase = (size_t)lc * N_DIM + lh * 16;

    // phase-1 mapping: tid = n*16 + cg
    const int p1n  = tid >> 4;
    const int p1cg = tid & 15;

    // ---- prologue: mu, zero accum, first tile ----
    #pragma unroll
    for (int it = 0; it < 4; ++it) {
        int i = it * 512 + tid;      // 2048 mu elems
        s_mu[MU(i >> 3) + (i & 7)] = g_mu[b * (C_DIM * K_DIM) + i];
    }
    #pragma unroll
    for (int it = 0; it < 8; ++it) s_M[it * 512 + tid] = 0.0f;
    if (tid < 8) s_S[tid] = 0.0f;

    int t0 = blockIdx.x;             // first tile index
    float4 p0, p1, p2, p3;
    {
        const float* g = xb + gbase + (size_t)t0 * NB;
        p0 = *(const float4*)(g + 0);  p1 = *(const float4*)(g + 4);
        p2 = *(const float4*)(g + 8);  p3 = *(const float4*)(g + 12);
        float* d = sm + SX(lc, lh * 16);
        d[0]=p0.x; d[1]=p0.y; d[2]=p0.z; d[3]=p0.w;
        d[4]=p1.x; d[5]=p1.y; d[6]=p1.z; d[7]=p1.w;
        d[8]=p2.x; d[9]=p2.y; d[10]=p2.z; d[11]=p2.w;
        d[12]=p3.x; d[13]=p3.y; d[14]=p3.z; d[15]=p3.w;
    }
    if (t0 + GR < NTILES) {
        const float* g = xb + gbase + (size_t)(t0 + GR) * NB;
        p0 = *(const float4*)(g + 0);  p1 = *(const float4*)(g + 4);
        p2 = *(const float4*)(g + 8);  p3 = *(const float4*)(g + 12);
    }
    __syncthreads();

    int cur = 0;
    for (int t = t0; t < NTILES; t += GR) {
        float* s_x = sm + cur * SX_SIZE;

        // ================= phase 1 =================
        float2 a0 = {0.f,0.f}, a1 = {0.f,0.f}, a2 = {0.f,0.f}, a3 = {0.f,0.f};
        {
            const float* xp = s_x + p1cg * 530 + p1n;     // 528 + 2 skew
            const float* mp = s_mu + p1cg * 132;
            #pragma unroll
            for (int i = 0; i < 16; ++i) {
                float  xv = xp[i * 33];
                float2 xs = make_float2(xv, xv);
                float4 ma = *(const float4*)(mp + i * 8);
                float4 mb = *(const float4*)(mp + i * 8 + 4);
                a0 = ffma2(xs, make_float2(ma.x, ma.y), a0);
                a1 = ffma2(xs, make_float2(ma.z, ma.w), a1);
                a2 = ffma2(xs, make_float2(mb.x, mb.y), a2);
                a3 = ffma2(xs, make_float2(mb.z, mb.w), a3);
            }
        }
        #pragma unroll
        for (int off = 1; off <= 8; off <<= 1) {
            a0.x += __shfl_xor_sync(~0u, a0.x, off);
            a0.y += __shfl_xor_sync(~0u, a0.y, off);
            a1.x += __shfl_xor_sync(~0u, a1.x, off);
            a1.y += __shfl_xor_sync(~0u, a1.y, off);
            a2.x += __shfl_xor_sync(~0u, a2.x, off);
            a2.y += __shfl_xor_sync(~0u, a2.y, off);
            a3.x += __shfl_xor_sync(~0u, a3.x, off);
            a3.y += __shfl_xor_sync(~0u, a3.y, off);
        }
        if (p1cg == 0) {
            float l0 = KAPPA*a0.x, l1 = KAPPA*a0.y, l2 = KAPPA*a1.x, l3 = KAPPA*a1.y;
            float l4 = KAPPA*a2.x, l5 = KAPPA*a2.y, l6 = KAPPA*a3.x, l7 = KAPPA*a3.y;
            float m = fmaxf(fmaxf(fmaxf(l0,l1), fmaxf(l2,l3)),
                            fmaxf(fmaxf(l4,l5), fmaxf(l6,l7)));
            float e0 = __expf(l0-m), e1 = __expf(l1-m), e2 = __expf(l2-m), e3 = __expf(l3-m);
            float e4 = __expf(l4-m), e5 = __expf(l5-m), e6 = __expf(l6-m), e7 = __expf(l7-m);
            float inv = 1.0f / (((e0+e1)+(e2+e3)) + ((e4+e5)+(e6+e7)));
            float4* zp = (float4*)(s_z + p1n * 8);
            zp[0] = make_float4(e0*inv, e1*inv, e2*inv, e3*inv);
            zp[1] = make_float4(e4*inv, e5*inv, e6*inv, e7*inv);
        }
        __syncthreads();

        // ================= phase 2 (+ prefetch STS/LDG) =================
        if (last && tid < 64) {
            int n = tid >> 1, q = tid & 1;
            float4 zv = *(const float4*)(s_z + n * 8 + q * 4);
            *(float4*)(z_out + ((size_t)b * N_DIM + (size_t)t * NB + n) * 8 + q * 4) = zv;
        }
        if (tid < 8) {   // S accumulation for this tile
            float s = 0.f;
            #pragma unroll
            for (int n = 0; n < NB; ++n) s += s_z[n * 8 + tid];
            s_S[tid] += s;
        }
        {
            float2 m0 = {0.f,0.f}, m1 = {0.f,0.f}, m2 = {0.f,0.f}, m3 = {0.f,0.f};
            const float*  xr = s_x + SX(lc, lh * 16);
            const float4* zz = (const float4*)(s_z + lh * 128);
            #pragma unroll
            for (int j = 0; j < 16; ++j) {
                float  xv = xr[j];
                float2 xs = make_float2(xv, xv);
                float4 za = zz[2*j], zb = zz[2*j+1];
                m0 = ffma2(xs, make_float2(za.x, za.y), m0);
                m1 = ffma2(xs, make_float2(za.z, za.w), m1);
                m2 = ffma2(xs, make_float2(zb.x, zb.y), m2);
                m3 = ffma2(xs, make_float2(zb.z, zb.w), m3);
            }
            float4* Mp = (float4*)(s_M + ((lh << 11) | (lc << 3)));
            float4 old0 = Mp[0], old1 = Mp[1];
            Mp[0] = make_float4(old0.x+m0.x, old0.y+m0.y, old0.z+m1.x, old0.w+m1.y);
            Mp[1] = make_float4(old1.x+m2.x, old1.y+m2.y, old1.z+m3.x, old1.w+m3.y);
        }
        // stage tile t+GR into the other buffer; prefetch t+2*GR
        if (t + GR < NTILES) {
            float* d = sm + (cur ^ 1) * SX_SIZE + SX(lc, lh * 16);
            d[0]=p0.x; d[1]=p0.y; d[2]=p0.z; d[3]=p0.w;
            d[4]=p1.x; d[5]=p1.y; d[6]=p1.z; d[7]=p1.w;
            d[8]=p2.x; d[9]=p2.y; d[10]=p2.z; d[11]=p2.w;
            d[12]=p3.x; d[13]=p3.y; d[14]=p3.z; d[15]=p3.w;
            if (t + 2 * GR < NTILES) {
                const float* g = xb + gbase + (size_t)(t + 2 * GR) * NB;
                p0 = *(const float4*)(g + 0);  p1 = *(const float4*)(g + 4);
                p2 = *(const float4*)(g + 8);  p3 = *(const float4*)(g + 12);
            }
        }
        __syncthreads();
        cur ^= 1;
    }

    // ---- epilogue: flush block-local accumulators ----
    if (tid < 8) atomicAdd(g_S + b * K_DIM + tid, s_S[tid]);
    #pragma unroll
    for (int it = 0; it < 4; ++it) {
        int i = it * 512 + tid;          // (c,k) pair index, 2048 total
        float v = s_M[i] + s_M[2048 + i];
        atomicAdd(g_M + b * (C_DIM * K_DIM) + i, v);
    }
}

__global__ void finalize_kernel(int last, float* __restrict__ mu_out) {
    const int k = blockIdx.x;
    const int b = blockIdx.y;
    const int c = threadIdx.x;
    __shared__ float red[256];

    float S = g_S[b * K_DIM + k];
    float val = g_M[((size_t)b * C_DIM + c) * K_DIM + k] / (1e-6f + S);

    red[c] = val * val;
    __syncthreads();
    for (int s = 128; s > 0; s >>= 1) {
        if (c < s) red[c] += red[c + s];
        __syncthreads();
    }
    float m = val / (1e-6f + sqrtf(red[0]));

    g_mu[((size_t)b * C_DIM + c) * K_DIM + k] = m;
    g_M [((size_t)b * C_DIM + c) * K_DIM + k] = 0.0f;
    if (c == 0) g_S[b * K_DIM + k] = 0.0f;
    if (last) mu_out[((size_t)b * K_DIM + k) * C_DIM + c] = m;
}

__global__ void zdiv_kernel(float* __restrict__ z) {
    int idx = blockIdx.x * blockDim.x + threadIdx.x;
    if (idx < B_DIM * N_DIM * K_DIM) {
        int k = idx & 7;
        int b = idx >> 17;
        z[idx] = z[idx] / (1e-6f + g_S[b * K_DIM + k]);
    }
}

extern "C" void kernel_launch(void* const* d_in, const int* in_sizes, int n_in,
                              void* d_out, int out_size) {
    const float* x     = (const float*)d_in[0];
    const float* mu_in = (const float*)d_in[1];
    float* out    = (float*)d_out;
    float* mu_out = out;
    float* z_out  = out + B_DIM * K_DIM * C_DIM;

    cudaFuncSetAttribute(em_stage, cudaFuncAttributeMaxDynamicSharedMemorySize, SMEM_BYTES);

    init_kernel<<<128, 256>>>(mu_in);
    for (int s = 0; s < NSTAGES; ++s) {
        int last = (s == NSTAGES - 1);
        em_stage<<<dim3(GR, B_DIM), 512, SMEM_BYTES>>>(x, last, z_out);
        if (last) zdiv_kernel<<<(B_DIM * N_DIM * K_DIM) / 256, 256>>>(z_out);
        finalize_kernel<<<dim3(K_DIM, B_DIM), 256>>>(last, mu_out);
    }
}

// round 5
// speedup vs baseline: 1.4827x; 1.4827x over previous
#include <cuda_runtime.h>

#define B_DIM 16
#define C_DIM 256
#define N_DIM 16384
#define K_DIM 8
#define NB 32
#define NTILES (N_DIM / NB)   // 512
#define GR 18
#define NSTAGES 10
#define KAPPA 20.0f

// ---- smem layout (floats) ----
// s_x[2]  : addr(c,n) = c*33 + n            (conflict-free p1/p2/STS)
// s_part  : [w][n][k] addr = w*272 + n*8 + (k ^ ((n>>2)&7))  (1-wf write & read)
// s_mu    : [c][k] plain (broadcast reads)
// s_z     : [n][k] addr = n*8 + 4*(n>>4) + k (h-halves -> distinct banks)
#define SX_STRIDE 33
#define SX_SIZE (C_DIM * SX_STRIDE)          // 8448
#define PART_STRIDE 272
#define PART_OFF (2 * SX_SIZE)               // 16896
#define PART_SIZE (16 * PART_STRIDE)         // 4352
#define MU_OFF (PART_OFF + PART_SIZE)        // 21248
#define Z_OFF (MU_OFF + C_DIM * K_DIM)       // 23296
#define Z_SIZE 264
#define S_OFF (Z_OFF + Z_SIZE)               // 23560
#define SM_FLOATS (S_OFF + 8)
#define SMEM_BYTES (SM_FLOATS * 4)           // ~94.3 KB

__device__ float g_mu[B_DIM * C_DIM * K_DIM];
__device__ float g_M [B_DIM * C_DIM * K_DIM];
__device__ float g_S [B_DIM * K_DIM];

__device__ __forceinline__ float2 ffma2(float2 a, float2 b, float2 c) {
    float2 d;
    asm("fma.rn.f32x2 %0, %1, %2, %3;"
        : "=l"(reinterpret_cast<unsigned long long&>(d))
        : "l"(reinterpret_cast<unsigned long long&>(a)),
          "l"(reinterpret_cast<unsigned long long&>(b)),
          "l"(reinterpret_cast<unsigned long long&>(c)));
    return d;
}

__global__ void init_kernel(const float* __restrict__ mu_in) {
    int idx = blockIdx.x * blockDim.x + threadIdx.x;
    if (idx < B_DIM * C_DIM * K_DIM) {
        g_mu[idx] = mu_in[idx & (C_DIM * K_DIM - 1)];
        g_M[idx]  = 0.0f;
    }
    if (idx < B_DIM * K_DIM) g_S[idx] = 0.0f;
}

__global__ __launch_bounds__(512, 2)
void em_stage(const float* __restrict__ x, int last, float* __restrict__ z_out) {
    extern __shared__ float sm[];
    float* s_part = sm + PART_OFF;
    float* s_mu   = sm + MU_OFF;
    float* s_z    = sm + Z_OFF;
    float* s_S    = sm + S_OFF;

    const int tid  = threadIdx.x;
    const int b    = blockIdx.y;
    const float* xb = x + (size_t)b * C_DIM * N_DIM;

    const int lc = tid >> 1, lh = tid & 1;            // loader / phase-2 mapping
    const int warp = tid >> 5, lane = tid & 31;       // phase-1: c-slice per warp, n=lane
    const int rw = tid & 1, rk = (tid >> 1) & 7, rn = tid >> 4;  // reduce mapping

    #pragma unroll
    for (int it = 0; it < 4; ++it) {
        int i = it * 512 + tid;
        s_mu[i] = g_mu[b * (C_DIM * K_DIM) + i];
    }
    if (tid < 8) s_S[tid] = 0.0f;

    // register accumulators (flushed once at the end)
    float2 M0 = {0.f,0.f}, M1 = {0.f,0.f}, M2 = {0.f,0.f}, M3 = {0.f,0.f};
    float Sacc = 0.0f;

    const size_t gbase = (size_t)lc * N_DIM + lh * 16;
    const int t0 = blockIdx.x;

    // prologue: tile t0 -> buffer 0; prefetch t0+GR into regs
    float4 r0, r1, r2, r3;
    {
        const float* g = xb + gbase + (size_t)t0 * NB;
        r0 = *(const float4*)(g + 0);  r1 = *(const float4*)(g + 4);
        r2 = *(const float4*)(g + 8);  r3 = *(const float4*)(g + 12);
        float* d = sm + lc * SX_STRIDE + lh * 16;
        d[0]=r0.x; d[1]=r0.y; d[2]=r0.z; d[3]=r0.w;
        d[4]=r1.x; d[5]=r1.y; d[6]=r1.z; d[7]=r1.w;
        d[8]=r2.x; d[9]=r2.y; d[10]=r2.z; d[11]=r2.w;
        d[12]=r3.x; d[13]=r3.y; d[14]=r3.z; d[15]=r3.w;
    }
    if (t0 + GR < NTILES) {
        const float* g = xb + gbase + (size_t)(t0 + GR) * NB;
        r0 = *(const float4*)(g + 0);  r1 = *(const float4*)(g + 4);
        r2 = *(const float4*)(g + 8);  r3 = *(const float4*)(g + 12);
    }
    __syncthreads();

    int cur = 0;
    for (int t = t0; t < NTILES; t += GR) {
        const float* sx = sm + cur * SX_SIZE;

        // ===== phase 1: partial logits for c-slice [16*warp, 16*warp+16) =====
        float2 a0 = {0.f,0.f}, a1 = {0.f,0.f}, a2 = {0.f,0.f}, a3 = {0.f,0.f};
        {
            const float*  xp = sx + warp * (16 * SX_STRIDE) + lane;
            const float4* mp = (const float4*)(s_mu + warp * 16 * 8);
            #pragma unroll
            for (int i = 0; i < 16; ++i) {
                float  xv = xp[i * SX_STRIDE];
                float2 xs = make_float2(xv, xv);
                float4 m0 = mp[2*i], m1 = mp[2*i+1];   // broadcast reads
                a0 = ffma2(xs, make_float2(m0.x, m0.y), a0);
                a1 = ffma2(xs, make_float2(m0.z, m0.w), a1);
                a2 = ffma2(xs, make_float2(m1.x, m1.y), a2);
                a3 = ffma2(xs, make_float2(m1.z, m1.w), a3);
            }
        }
        {   // swizzled partial write (1 wf per STS.32)
            float* pb = s_part + warp * PART_STRIDE + lane * 8;
            int sw = (lane >> 2) & 7;
            pb[0^sw] = a0.x; pb[1^sw] = a0.y; pb[2^sw] = a1.x; pb[3^sw] = a1.y;
            pb[4^sw] = a2.x; pb[5^sw] = a2.y; pb[6^sw] = a3.x; pb[7^sw] = a3.y;
        }
        __syncthreads();

        // ===== reduce over 16 warps + softmax (2 threads per (n,k)) =====
        {
            int col = rn * 8 + (rk ^ ((rn >> 2) & 7));
            float v = 0.f;
            #pragma unroll
            for (int i = 0; i < 8; ++i)
                v += s_part[(rw + 2*i) * PART_STRIDE + col];
            v += __shfl_xor_sync(~0u, v, 1);
            v *= KAPPA;
            float mx = v;
            mx = fmaxf(mx, __shfl_xor_sync(~0u, mx, 2));
            mx = fmaxf(mx, __shfl_xor_sync(~0u, mx, 4));
            mx = fmaxf(mx, __shfl_xor_sync(~0u, mx, 8));
            float e = __expf(v - mx);
            float s = e;
            s += __shfl_xor_sync(~0u, s, 2);
            s += __shfl_xor_sync(~0u, s, 4);
            s += __shfl_xor_sync(~0u, s, 8);
            float z = e / s;
            if (rw == 0) {
                s_z[rn * 8 + ((rn >> 4) << 2) + rk] = z;
                Sacc += z;
                if (last)
                    z_out[((size_t)b * N_DIM + (size_t)t * NB + rn) * 8 + rk] = z;
            }
        }
        __syncthreads();

        // ===== stage next tile + prefetch next-next =====
        if (t + GR < NTILES) {
            float* d = sm + (cur ^ 1) * SX_SIZE + lc * SX_STRIDE + lh * 16;
            d[0]=r0.x; d[1]=r0.y; d[2]=r0.z; d[3]=r0.w;
            d[4]=r1.x; d[5]=r1.y; d[6]=r1.z; d[7]=r1.w;
            d[8]=r2.x; d[9]=r2.y; d[10]=r2.z; d[11]=r2.w;
            d[12]=r3.x; d[13]=r3.y; d[14]=r3.z; d[15]=r3.w;
            if (t + 2 * GR < NTILES) {
                const float* g = xb + gbase + (size_t)(t + 2 * GR) * NB;
                r0 = *(const float4*)(g + 0);  r1 = *(const float4*)(g + 4);
                r2 = *(const float4*)(g + 8);  r3 = *(const float4*)(g + 12);
            }
        }

        // ===== phase 2: register M accumulation =====
        {
            const float* xr = sx + lc * SX_STRIDE + lh * 16;
            const float* zr = s_z + lh * 132;       // 16*8 + 4 pad
            #pragma unroll
            for (int j = 0; j < 16; ++j) {
                float  xv = xr[j];
                float2 xs = make_float2(xv, xv);
                float4 za = *(const float4*)(zr + 8*j);
                float4 zb = *(const float4*)(zr + 8*j + 4);
                M0 = ffma2(xs, make_float2(za.x, za.y), M0);
                M1 = ffma2(xs, make_float2(za.z, za.w), M1);
                M2 = ffma2(xs, make_float2(zb.x, zb.y), M2);
                M3 = ffma2(xs, make_float2(zb.z, zb.w), M3);
            }
        }
        __syncthreads();
        cur ^= 1;
    }

    // ---- flush M: combine h-pairs via shfl, even threads write ----
    M0.x += __shfl_xor_sync(~0u, M0.x, 1);  M0.y += __shfl_xor_sync(~0u, M0.y, 1);
    M1.x += __shfl_xor_sync(~0u, M1.x, 1);  M1.y += __shfl_xor_sync(~0u, M1.y, 1);
    M2.x += __shfl_xor_sync(~0u, M2.x, 1);  M2.y += __shfl_xor_sync(~0u, M2.y, 1);
    M3.x += __shfl_xor_sync(~0u, M3.x, 1);  M3.y += __shfl_xor_sync(~0u, M3.y, 1);
    if (lh == 0) {
        float* Mp = g_M + ((size_t)b * C_DIM + lc) * K_DIM;
        atomicAdd(Mp + 0, M0.x); atomicAdd(Mp + 1, M0.y);
        atomicAdd(Mp + 2, M1.x); atomicAdd(Mp + 3, M1.y);
        atomicAdd(Mp + 4, M2.x); atomicAdd(Mp + 5, M2.y);
        atomicAdd(Mp + 6, M3.x); atomicAdd(Mp + 7, M3.y);
    }
    // ---- flush S ----
    Sacc += __shfl_xor_sync(~0u, Sacc, 16);
    Sacc += __shfl_xor_sync(~0u, Sacc, 1);
    if ((lane & 0x11) == 0) atomicAdd(s_S + rk, Sacc);
    __syncthreads();
    if (tid < 8) atomicAdd(g_S + b * K_DIM + tid, s_S[tid]);
}

__global__ void finalize_kernel(int last, float* __restrict__ mu_out) {
    const int k = blockIdx.x;
    const int b = blockIdx.y;
    const int c = threadIdx.x;
    __shared__ float red[256];

    float S = g_S[b * K_DIM + k];
    float val = g_M[((size_t)b * C_DIM + c) * K_DIM + k] / (1e-6f + S);

    red[c] = val * val;
    __syncthreads();
    for (int s = 128; s > 0; s >>= 1) {
        if (c < s) red[c] += red[c + s];
        __syncthreads();
    }
    float m = val / (1e-6f + sqrtf(red[0]));

    g_mu[((size_t)b * C_DIM + c) * K_DIM + k] = m;
    g_M [((size_t)b * C_DIM + c) * K_DIM + k] = 0.0f;
    if (c == 0) g_S[b * K_DIM + k] = 0.0f;
    if (last) mu_out[((size_t)b * K_DIM + k) * C_DIM + c] = m;
}

__global__ void zdiv_kernel(float* __restrict__ z) {
    int idx = blockIdx.x * blockDim.x + threadIdx.x;
    if (idx < B_DIM * N_DIM * K_DIM) {
        int k = idx & 7;
        int b = idx >> 17;
        z[idx] = z[idx] / (1e-6f + g_S[b * K_DIM + k]);
    }
}

extern "C" void kernel_launch(void* const* d_in, const int* in_sizes, int n_in,
                              void* d_out, int out_size) {
    const float* x     = (const float*)d_in[0];
    const float* mu_in = (const float*)d_in[1];
    float* out    = (float*)d_out;
    float* mu_out = out;
    float* z_out  = out + B_DIM * K_DIM * C_DIM;

    cudaFuncSetAttribute(em_stage, cudaFuncAttributeMaxDynamicSharedMemorySize, SMEM_BYTES);

    init_kernel<<<128, 256>>>(mu_in);
    for (int s = 0; s < NSTAGES; ++s) {
        int last = (s == NSTAGES - 1);
        em_stage<<<dim3(GR, B_DIM), 512, SMEM_BYTES>>>(x, last, z_out);
        if (last) zdiv_kernel<<<(B_DIM * N_DIM * K_DIM) / 256, 256>>>(z_out);
        finalize_kernel<<<dim3(K_DIM, B_DIM), 256>>>(last, mu_out);
    }
}